// round 6
// baseline (speedup 1.0000x reference)
#include <cuda_runtime.h>
#include <cstddef>
#include <cstdint>

// Problem constants
#define BB 8
#define TT 2048
#define DD 1024
#define HH 8
#define NN 32
#define MROWS (BB*TT)          // 16384
#define HN (HH*NN)             // 256

// ---------------------------------------------------------------------------
// Scratch (no cudaMalloc allowed) — __device__ globals.
// ---------------------------------------------------------------------------
__device__ float g_xp  [(size_t)MROWS * DD];   // 64 MB
__device__ float g_k   [(size_t)MROWS * HN];   // 16 MB
__device__ float g_v   [(size_t)MROWS * HN];
__device__ float g_q   [(size_t)MROWS * HN];
__device__ float g_beta[(size_t)MROWS * HN];
__device__ float g_cell[(size_t)MROWS * HN];

// ---------------------------------------------------------------------------
// bf16x2 split helpers.
//   x = hi + lo:  hi = fp32 with low 16 mantissa bits zeroed (== bf16 truncation,
//   exactly representable in bf16), lo = bf16(x - hi) (residual, exact subtract).
//   Combined mantissa ~17 bits; dropped lo*lo term ~2^-16 relative.
// ---------------------------------------------------------------------------
__device__ __forceinline__ float trunc_hi(float x) {
    return __uint_as_float(__float_as_uint(x) & 0xFFFF0000u);
}
// pack bf16(hi of e0), bf16(hi of e1) into one .b32: lo half = e0, hi half = e1
__device__ __forceinline__ unsigned pack_hi_pair(float e0, float e1) {
    return __byte_perm(__float_as_uint(e0), __float_as_uint(e1), 0x7632);
}
// pack bf16(l0), bf16(l1) (round-to-nearest) into .b32: lo half = l0
__device__ __forceinline__ unsigned pack_lo_pair(float l0, float l1) {
    unsigned d;
    asm("cvt.rn.bf16x2.f32 %0, %1, %2;" : "=r"(d) : "f"(l1), "f"(l0));
    return d;
}

__device__ __forceinline__ void mma_bf16(float d[4],
                                         unsigned a0, unsigned a1,
                                         unsigned a2, unsigned a3,
                                         unsigned b0, unsigned b1) {
    asm("mma.sync.aligned.m16n8k16.row.col.f32.bf16.bf16.f32 "
        "{%0,%1,%2,%3}, {%4,%5,%6,%7}, {%8,%9}, {%0,%1,%2,%3};"
        : "+f"(d[0]), "+f"(d[1]), "+f"(d[2]), "+f"(d[3])
        : "r"(a0), "r"(a1), "r"(a2), "r"(a3), "r"(b0), "r"(b1));
}

// ---------------------------------------------------------------------------
// bf16x2-compensated tensor-core GEMM: C[M,Nout] = epi( A[M,K] @ W[Nout,K]^T )
// Block tile 128x128, BK=16, 8 warps (2 M x 4 N), warp tile 64x32.
// smem: 4 planes (A_hi, A_lo, W_hi, W_lo), each 128 rows x 12 u32 (8 data+4 pad),
// double buffered = 48KB exactly. Each u32 = bf16 pair along K.
// Per k16 per 16x8 subtile: 3 mma (hh, lh, hl).
// epi: 0 identity, 1 silu, 2 sigmoid(acc + bias[col])
// ---------------------------------------------------------------------------
#define PLW 12                       // plane row stride in u32
#define PLANE (128 * PLW)            // u32 per plane

// stage 8 consecutive K-floats of one row into hi/lo planes (4 words each)
__device__ __forceinline__ void stage8(const float* __restrict__ gp,
                                       unsigned* __restrict__ hi,
                                       unsigned* __restrict__ lo) {
    float4 x0 = *reinterpret_cast<const float4*>(gp);
    float4 x1 = *reinterpret_cast<const float4*>(gp + 4);
    hi[0] = pack_hi_pair(x0.x, x0.y);
    hi[1] = pack_hi_pair(x0.z, x0.w);
    hi[2] = pack_hi_pair(x1.x, x1.y);
    hi[3] = pack_hi_pair(x1.z, x1.w);
    lo[0] = pack_lo_pair(x0.x - trunc_hi(x0.x), x0.y - trunc_hi(x0.y));
    lo[1] = pack_lo_pair(x0.z - trunc_hi(x0.z), x0.w - trunc_hi(x0.w));
    lo[2] = pack_lo_pair(x1.x - trunc_hi(x1.x), x1.y - trunc_hi(x1.y));
    lo[3] = pack_lo_pair(x1.z - trunc_hi(x1.z), x1.w - trunc_hi(x1.w));
}

__device__ __forceinline__ void mma_gemm_core(
    const float* __restrict__ A, const float* __restrict__ W,
    float* __restrict__ C, const float* __restrict__ bias,
    int epi, int Nout, int K, int row0, int col0)
{
    // [buffer][plane][row*PLW + word]: planes = A_hi, A_lo, W_hi, W_lo
    __shared__ unsigned sm[2][4 * PLANE];

    const int tid  = threadIdx.x;
    const int wid  = tid >> 5;
    const int lane = tid & 31;
    const int g    = lane >> 2;        // fragment group row 0..7
    const int c    = lane & 3;         // fragment k-pair 0..3
    const int wm   = (wid & 1) * 64;   // warp row offset
    const int wn   = (wid >> 1) * 32;  // warp col offset

    // Staging: each thread loads 8 floats (one row, k-offset 0 or 8) per operand.
    const int lr = tid >> 1;           // 0..127
    const int le = (tid & 1) * 8;      // element offset in chunk
    const int wb = (tid & 1) * 4;      // word offset in plane row
    const float* Ap = A + (size_t)(row0 + lr) * K + le;
    const float* Wp = W + (size_t)(col0 + lr) * K + le;
    const int srow = lr * PLW + wb;

    float acc[4][4][4];
#pragma unroll
    for (int mt = 0; mt < 4; ++mt)
#pragma unroll
        for (int nt = 0; nt < 4; ++nt)
#pragma unroll
            for (int e = 0; e < 4; ++e) acc[mt][nt][e] = 0.f;

    const int nchunks = K / 16;

    // prologue: stage chunk 0 into buffer 0
    stage8(Ap, &sm[0][0 * PLANE + srow], &sm[0][1 * PLANE + srow]);
    stage8(Wp, &sm[0][2 * PLANE + srow], &sm[0][3 * PLANE + srow]);
    __syncthreads();

    for (int chunk = 0; chunk < nchunks; ++chunk) {
        const int cur = chunk & 1;
        const bool more = (chunk + 1 < nchunks);

        // prefetch next chunk's globals into registers
        float4 pa0, pa1, pw0, pw1;
        if (more) {
            const int ko = (chunk + 1) * 16;
            pa0 = *reinterpret_cast<const float4*>(Ap + ko);
            pa1 = *reinterpret_cast<const float4*>(Ap + ko + 4);
            pw0 = *reinterpret_cast<const float4*>(Wp + ko);
            pw1 = *reinterpret_cast<const float4*>(Wp + ko + 4);
        }

        const unsigned* Ahi = &sm[cur][0 * PLANE];
        const unsigned* Alo = &sm[cur][1 * PLANE];
        const unsigned* Whi = &sm[cur][2 * PLANE];
        const unsigned* Wlo = &sm[cur][3 * PLANE];

#pragma unroll
        for (int mh = 0; mh < 2; ++mh) {
            unsigned ah[2][4], al[2][4];
#pragma unroll
            for (int m2 = 0; m2 < 2; ++m2) {
                const int rb = wm + (mh * 2 + m2) * 16;
                const int r0 = (rb + g) * PLW;
                const int r1 = (rb + 8 + g) * PLW;
                ah[m2][0] = Ahi[r0 + c];     ah[m2][1] = Ahi[r1 + c];
                ah[m2][2] = Ahi[r0 + 4 + c]; ah[m2][3] = Ahi[r1 + 4 + c];
                al[m2][0] = Alo[r0 + c];     al[m2][1] = Alo[r1 + c];
                al[m2][2] = Alo[r0 + 4 + c]; al[m2][3] = Alo[r1 + 4 + c];
            }
#pragma unroll
            for (int nt = 0; nt < 4; ++nt) {
                const int wr = (wn + nt * 8 + g) * PLW;
                const unsigned bh0 = Whi[wr + c];
                const unsigned bh1 = Whi[wr + 4 + c];
                const unsigned bl0 = Wlo[wr + c];
                const unsigned bl1 = Wlo[wr + 4 + c];
#pragma unroll
                for (int m2 = 0; m2 < 2; ++m2) {
                    float* d = acc[mh * 2 + m2][nt];
                    mma_bf16(d, ah[m2][0], ah[m2][1], ah[m2][2], ah[m2][3], bh0, bh1); // hh
                    mma_bf16(d, al[m2][0], al[m2][1], al[m2][2], al[m2][3], bh0, bh1); // lh
                    mma_bf16(d, ah[m2][0], ah[m2][1], ah[m2][2], ah[m2][3], bl0, bl1); // hl
                }
            }
        }

        if (more) {
            const int nxt = cur ^ 1;
            float4 t;
            unsigned* ahd = &sm[nxt][0 * PLANE + srow];
            unsigned* ald = &sm[nxt][1 * PLANE + srow];
            unsigned* whd = &sm[nxt][2 * PLANE + srow];
            unsigned* wld = &sm[nxt][3 * PLANE + srow];
            t = pa0;
            ahd[0] = pack_hi_pair(t.x, t.y); ahd[1] = pack_hi_pair(t.z, t.w);
            ald[0] = pack_lo_pair(t.x - trunc_hi(t.x), t.y - trunc_hi(t.y));
            ald[1] = pack_lo_pair(t.z - trunc_hi(t.z), t.w - trunc_hi(t.w));
            t = pa1;
            ahd[2] = pack_hi_pair(t.x, t.y); ahd[3] = pack_hi_pair(t.z, t.w);
            ald[2] = pack_lo_pair(t.x - trunc_hi(t.x), t.y - trunc_hi(t.y));
            ald[3] = pack_lo_pair(t.z - trunc_hi(t.z), t.w - trunc_hi(t.w));
            t = pw0;
            whd[0] = pack_hi_pair(t.x, t.y); whd[1] = pack_hi_pair(t.z, t.w);
            wld[0] = pack_lo_pair(t.x - trunc_hi(t.x), t.y - trunc_hi(t.y));
            wld[1] = pack_lo_pair(t.z - trunc_hi(t.z), t.w - trunc_hi(t.w));
            t = pw1;
            whd[2] = pack_hi_pair(t.x, t.y); whd[3] = pack_hi_pair(t.z, t.w);
            wld[2] = pack_lo_pair(t.x - trunc_hi(t.x), t.y - trunc_hi(t.y));
            wld[3] = pack_lo_pair(t.z - trunc_hi(t.z), t.w - trunc_hi(t.w));
        }
        __syncthreads();
    }

    // Epilogue: thread owns (row=g(+8), col=2c(+1)) of each 16x8 sub-tile.
#pragma unroll
    for (int mt = 0; mt < 4; ++mt) {
        const int r0 = row0 + wm + mt * 16 + g;
#pragma unroll
        for (int nt = 0; nt < 4; ++nt) {
            const int cc = col0 + wn + nt * 8 + 2 * c;
            float d0 = acc[mt][nt][0], d1 = acc[mt][nt][1];
            float d2 = acc[mt][nt][2], d3 = acc[mt][nt][3];
            if (epi == 1) {
                d0 = d0 / (1.f + __expf(-d0));
                d1 = d1 / (1.f + __expf(-d1));
                d2 = d2 / (1.f + __expf(-d2));
                d3 = d3 / (1.f + __expf(-d3));
            } else if (epi == 2) {
                const float b0 = bias[cc], b1 = bias[cc + 1];
                d0 = 1.f / (1.f + __expf(-(d0 + b0)));
                d1 = 1.f / (1.f + __expf(-(d1 + b1)));
                d2 = 1.f / (1.f + __expf(-(d2 + b0)));
                d3 = 1.f / (1.f + __expf(-(d3 + b1)));
            }
            *reinterpret_cast<float2*>(C + (size_t)r0 * Nout + cc)       = make_float2(d0, d1);
            *reinterpret_cast<float2*>(C + (size_t)(r0 + 8) * Nout + cc) = make_float2(d2, d3);
        }
    }
}

template<int EPI>
__global__ void __launch_bounds__(256, 2)
gemm_awt(const float* __restrict__ A, const float* __restrict__ W,
         float* __restrict__ C, const float* __restrict__ bias,
         int Nout, int K)
{
    mma_gemm_core(A, W, C, bias, EPI, Nout, K, blockIdx.y * 128, blockIdx.x * 128);
}

struct ProjPtrs {
    const float* W[4];
    float*       C[4];
};

__global__ void __launch_bounds__(256, 2)
gemm_proj4(const float* __restrict__ A, ProjPtrs p, const float* __restrict__ bias,
           int Nout, int K)
{
    const int z = blockIdx.z;
    mma_gemm_core(A, p.W[z], p.C[z], bias, (z == 3) ? 2 : 0, Nout, K,
                  blockIdx.y * 128, blockIdx.x * 128);
}

// ---------------------------------------------------------------------------
// k-normalization (in place): kn = k / (||k|| + 1e-6), one warp per 32-vector.
// ---------------------------------------------------------------------------
__global__ void __launch_bounds__(256)
knorm_kernel(float* __restrict__ kk)
{
    const size_t r = (size_t)blockIdx.x * 8 + (threadIdx.x >> 5);
    const int j = threadIdx.x & 31;
    const size_t a = r * 32 + j;
    const float v = kk[a];
    float s2 = v * v;
#pragma unroll
    for (int o = 16; o > 0; o >>= 1) s2 += __shfl_xor_sync(0xffffffffu, s2, o);
    kk[a] = v / (sqrtf(s2) + 1e-6f);
}

// ---------------------------------------------------------------------------
// Barrier-free sequential scan: one WARP per (chain, state-row), lane = column.
// k pre-normalized, prefetch ring depth 4, dual interleaved shfl butterflies,
// tanh via __expf + __fdividef (MUFU rcp) — fast division off the long chain.
// ---------------------------------------------------------------------------
#define PF 4

__global__ void __launch_bounds__(256)
scan_kernel(const float* __restrict__ Kn, const float* __restrict__ Vp,
            const float* __restrict__ Qp, const float* __restrict__ Bp,
            float* __restrict__ cell, float* __restrict__ S_final, int writeS)
{
    const int g     = blockIdx.x * 8 + (threadIdx.x >> 5);  // global warp id
    const int chain = g >> 5;          // 0..63
    const int i     = g & 31;          // state row
    const int j     = threadIdx.x & 31;// state col
    const size_t cb = ((size_t)(chain >> 3) * TT) * HN + (size_t)(chain & 7) * NN;

    float pk[PF], pq[PF], pv[PF], pb[PF];
#pragma unroll
    for (int d = 0; d < PF; ++d) {
        const size_t a = cb + (size_t)d * HN;
        pk[d] = Kn[a + j]; pq[d] = Qp[a + j];
        pv[d] = Vp[a + i]; pb[d] = Bp[a + i];
    }

    float S = 0.f, sqp = 0.f;      // sqp: pending S·q partial from prev step
    size_t base = cb;

    for (int t = 0; t < TT; t += PF) {
#pragma unroll
        for (int u = 0; u < PF; ++u) {
            const int tcur = t + u;
            const int tpre = (tcur + PF < TT) ? (tcur + PF) : (TT - 1);
            const size_t pa = cb + (size_t)tpre * HN;
            const float nk = Kn[pa + j];
            const float nq = Qp[pa + j];
            const float nv = Vp[pa + i];
            const float nb = Bp[pa + i];

            // dual interleaved butterflies: current S·kn, previous S·q
            float uu = S * pk[u];
            float sv = sqp;
#pragma unroll
            for (int o = 16; o > 0; o >>= 1) {
                uu += __shfl_xor_sync(0xffffffffu, uu, o);
                sv += __shfl_xor_sync(0xffffffffu, sv, o);
            }
            // lazy store of previous step's output
            if (tcur > 0 && j == 0)
                cell[base - HN + i] = sv * sv * __fdividef(1.f, 1.f + __expf(-sv));

            // state update: S = tanh(beta_i*S + (v_i - S·kn)*kn_j)
            const float z = fmaf(pb[u], S, (pv[u] - uu) * pk[u]);
            const float e = __expf(2.f * z);
            S = 1.f - __fdividef(2.f, e + 1.f);
            sqp = S * pq[u];

            pk[u] = nk; pq[u] = nq; pv[u] = nv; pb[u] = nb;
            base += HN;
        }
    }

    float sv = sqp;
#pragma unroll
    for (int o = 16; o > 0; o >>= 1) sv += __shfl_xor_sync(0xffffffffu, sv, o);
    if (j == 0)
        cell[base - HN + i] = sv * sv * __fdividef(1.f, 1.f + __expf(-sv));

    if (writeS)
        S_final[((size_t)chain * NN + i) * NN + j] = S;
}

// ---------------------------------------------------------------------------
// Host launcher
// ---------------------------------------------------------------------------
extern "C" void kernel_launch(void* const* d_in, const int* in_sizes, int n_in,
                              void* d_out, int out_size)
{
    const float* x      = (const float*)d_in[0];
    const float* W_in   = (const float*)d_in[1];
    const float* W_k    = (const float*)d_in[2];
    const float* W_v    = (const float*)d_in[3];
    const float* W_q    = (const float*)d_in[4];
    const float* W_beta = (const float*)d_in[5];
    const float* b_beta = (const float*)d_in[6];
    const float* W_out  = (const float*)d_in[7];
    float* y = (float*)d_out;

    float *xp, *k, *v, *q, *bt, *cell;
    cudaGetSymbolAddress((void**)&xp,   g_xp);
    cudaGetSymbolAddress((void**)&k,    g_k);
    cudaGetSymbolAddress((void**)&v,    g_v);
    cudaGetSymbolAddress((void**)&q,    g_q);
    cudaGetSymbolAddress((void**)&bt,   g_beta);
    cudaGetSymbolAddress((void**)&cell, g_cell);

    const int M = MROWS;

    // 1. xp = silu(x @ W_in^T)     [16384,1024] = [16384,1024] x [1024,1024]^T
    gemm_awt<1><<<dim3(DD / 128, M / 128), 256>>>(x, W_in, xp, nullptr, DD, DD);

    // 2. fused projections (k, v, q, beta)   [16384,256] each
    ProjPtrs p;
    p.W[0] = W_k;  p.W[1] = W_v;  p.W[2] = W_q;  p.W[3] = W_beta;
    p.C[0] = k;    p.C[1] = v;    p.C[2] = q;    p.C[3] = bt;
    gemm_proj4<<<dim3(HN / 128, M / 128, 4), 256>>>(xp, p, b_beta, HN, DD);

    // 3. normalize k in place
    knorm_kernel<<<(MROWS * HH) / 8, 256>>>(k);

    // 4. sequential scan
    const size_t y_elems = (size_t)M * DD;
    const int writeS = (out_size >= (int)(y_elems + (size_t)BB * HH * NN * NN)) ? 1 : 0;
    scan_kernel<<<256, 256>>>(k, v, q, bt, cell, y + y_elems, writeS);

    // 5. y = cell @ W_out^T        [16384,1024] = [16384,256] x [1024,256]^T
    gemm_awt<0><<<dim3(DD / 128, M / 128), 256>>>(cell, W_out, y, nullptr, DD, HN);
}